// round 15
// baseline (speedup 1.0000x reference)
#include <cuda_runtime.h>
#include <cuda_fp16.h>
#include <cstdint>

// Problem constants
#define S_LEN 2048
#define BATCH 16
#define HID   1024
#define NCH   (BATCH*HID)        // 16384 channels
#define MTOT  (S_LEN*BATCH)      // 32768
#define KTOT  HID                // 1024
#define NTOT  (3*HID)            // 3072

// Scan chunking
#define NC 128
#define CS (S_LEN/NC)            // 16

// fp16 mma GEMM tiling: 128 x 256 CTA tile, 8 warps of 64x64
#define BM 128
#define BN 256
#define BKH 64                   // K halves per stage (=128B row)
#define STAGES 3
#define A_BYTES (BM*128)         // 16 KB
#define B_BYTES (BN*128)         // 32 KB
#define STG_BYTES (A_BYTES+B_BYTES)      // 48 KB
#define SMEM_BYTES (STAGES*STG_BYTES)    // 144 KB
#define KTILES (KTOT/BKH)        // 16

// Scratch (device globals only)
__device__ __half g_Yh[(size_t)MTOT*NTOT];    // 201 MB : pre-activations (fp16)
__device__ __half g_Xh[(size_t)MTOT*HID];     // 67 MB  : layer input (fp16)
__device__ __half g_Wh[(size_t)NTOT*KTOT];    // 6 MB   : current-layer W (fp16)
__device__ float  g_AB[(size_t)NC*NCH*2];     // 16 MB
__device__ float  g_carry[(size_t)NC*NCH];    // 8 MB

// ---------------------------------------------------------------------------
__device__ __forceinline__ void cp16(uint32_t smem, const void* gmem) {
    asm volatile("cp.async.cg.shared.global [%0], [%1], 16;\n" :: "r"(smem), "l"(gmem));
}
__device__ __forceinline__ void cp_commit() {
    asm volatile("cp.async.commit_group;\n" ::: "memory");
}

__device__ __forceinline__ void ldsm4(uint32_t* r, uint32_t addr) {
    asm volatile("ldmatrix.sync.aligned.m8n8.x4.shared.b16 {%0,%1,%2,%3}, [%4];"
                 : "=r"(r[0]), "=r"(r[1]), "=r"(r[2]), "=r"(r[3]) : "r"(addr));
}

__device__ __forceinline__ void mma_f16(float c[4], const uint32_t a[4], const uint32_t b[2]) {
    asm volatile(
        "mma.sync.aligned.m16n8k16.row.col.f32.f16.f16.f32 "
        "{%0,%1,%2,%3}, {%4,%5,%6,%7}, {%8,%9}, {%0,%1,%2,%3};\n"
        : "+f"(c[0]), "+f"(c[1]), "+f"(c[2]), "+f"(c[3])
        : "r"(a[0]), "r"(a[1]), "r"(a[2]), "r"(a[3]), "r"(b[0]), "r"(b[1]));
}

__device__ __forceinline__ float sigmoidf_(float v) { return 1.f / (1.f + __expf(-v)); }
__device__ __forceinline__ float tanhf_(float v)    { return 2.f / (1.f + __expf(-2.f * v)) - 1.f; }

// ---------------------------------------------------------------------------
// Embedding gather -> fp16
__global__ void qrnn_embed(const int* __restrict__ x, const float* __restrict__ emb) {
    int tid = blockIdx.x * blockDim.x + threadIdx.x;
    int m  = tid >> 7;
    int hv = tid & 127;
    int tok = x[m];
    const float4* src = reinterpret_cast<const float4*>(emb) + (size_t)tok * 256 + hv * 2;
    float4 f0 = src[0], f1 = src[1];
    __half2 h[4];
    h[0] = __floats2half2_rn(f0.x, f0.y);
    h[1] = __floats2half2_rn(f0.z, f0.w);
    h[2] = __floats2half2_rn(f1.x, f1.y);
    h[3] = __floats2half2_rn(f1.z, f1.w);
    *reinterpret_cast<uint4*>(g_Xh + (size_t)m * HID + hv * 8) = *reinterpret_cast<uint4*>(h);
}

// W (fp32) -> g_Wh (fp16)
__global__ void w_to_half(const float* __restrict__ W) {
    int tid = blockIdx.x * blockDim.x + threadIdx.x;
    const float4* src = reinterpret_cast<const float4*>(W) + (size_t)tid * 2;
    float4 f0 = src[0], f1 = src[1];
    __half2 h[4];
    h[0] = __floats2half2_rn(f0.x, f0.y);
    h[1] = __floats2half2_rn(f0.z, f0.w);
    h[2] = __floats2half2_rn(f1.x, f1.y);
    h[3] = __floats2half2_rn(f1.z, f1.w);
    *reinterpret_cast<uint4*>(g_Wh + (size_t)tid * 8) = *reinterpret_cast<uint4*>(h);
}

// ---------------------------------------------------------------------------
// Load one 48KB stage: A 128x64h + B 256x64h, SW128-swizzled (16B granules).
__device__ __forceinline__ void load_stage(const __half* __restrict__ Ag,
                                           const __half* __restrict__ Bg,
                                           uint32_t sstage, int tid, int k0h) {
#pragma unroll
    for (int i = 0; i < 4; i++) {           // A: 1024 16B-chunks
        int c = tid + 256 * i;
        int r = c >> 3, c8 = c & 7;
        cp16(sstage + r * 128 + ((c8 * 16) ^ ((r & 7) << 4)),
             Ag + (size_t)r * KTOT + k0h + c8 * 8);
    }
#pragma unroll
    for (int i = 0; i < 8; i++) {           // B: 2048 16B-chunks
        int c = tid + 256 * i;
        int r = c >> 3, c8 = c & 7;
        cp16(sstage + A_BYTES + r * 128 + ((c8 * 16) ^ ((r & 7) << 4)),
             Bg + (size_t)r * KTOT + k0h + c8 * 8);
    }
}

// ---------------------------------------------------------------------------
// fp16 GEMM: g_Yh[m,n] = sum_k g_Xh[m,k] * g_Wh[n,k]   (fp32 accumulate)
// 8 warps: wm in {0,1} (64 rows), wn in {0..3} (64 cols each).
__global__ void __launch_bounds__(256, 1) qrnn_gemm_h(int dummy) {
    extern __shared__ float sm[];
    uint32_t sb = (uint32_t)__cvta_generic_to_shared(sm);
    const int tid = threadIdx.x;
    const int lane = tid & 31;
    const int warp = tid >> 5;
    const int wm = warp & 1;
    const int wn = warp >> 1;

    const int bid = blockIdx.x;
    const int grp = bid / 192;                 // 16 supertiles of 16bm x 12bn
    const int w_  = bid % 192;
    const int bm  = grp * 16 + (w_ & 15);      // 0..255
    const int bn  = w_ >> 4;                   // 0..11

    const __half* Ag = g_Xh + (size_t)bm * BM * KTOT;
    const __half* Bg = g_Wh + (size_t)bn * BN * KTOT;

    const uint32_t xorp = (uint32_t)((lane & 7) << 4);
    const uint32_t aRowOff = (uint32_t)((wm * 64 + (lane & 7) + ((lane >> 3) & 1) * 8) * 128);
    const uint32_t bRowOff = (uint32_t)((wn * 64 + (lane & 7) + ((lane >> 4) & 1) * 8) * 128);
    const uint32_t akb = (uint32_t)((lane >> 4) * 16);        // A: khi select
    const uint32_t bkb = (uint32_t)(((lane >> 3) & 1) * 16);  // B: khi select

    float acc[4][8][4];
#pragma unroll
    for (int i = 0; i < 4; i++)
#pragma unroll
        for (int j = 0; j < 8; j++)
#pragma unroll
            for (int r = 0; r < 4; r++) acc[i][j][r] = 0.f;

#pragma unroll
    for (int s = 0; s < STAGES; s++) {
        load_stage(Ag, Bg, sb + s * STG_BYTES, tid, s * BKH);
        cp_commit();
    }

    for (int kt = 0; kt < KTILES; kt++) {
        asm volatile("cp.async.wait_group 2;\n" ::: "memory");
        __syncthreads();

        const uint32_t sA = sb + (uint32_t)(kt % STAGES) * STG_BYTES;
        const uint32_t sB = sA + A_BYTES;

#pragma unroll
        for (int ks = 0; ks < 4; ks++) {
            const uint32_t aK = (uint32_t)(ks * 32 + akb) ^ xorp;
            const uint32_t bK = (uint32_t)(ks * 32 + bkb) ^ xorp;
            uint32_t af[4][4], bf[4][4];
#pragma unroll
            for (int mt = 0; mt < 4; mt++)
                ldsm4(af[mt], sA + aRowOff + mt * 2048 + aK);
#pragma unroll
            for (int np = 0; np < 4; np++)          // 4 x 16 n-rows = 64 cols
                ldsm4(bf[np], sB + bRowOff + np * 2048 + bK);
#pragma unroll
            for (int mt = 0; mt < 4; mt++)
#pragma unroll
                for (int nt = 0; nt < 8; nt++)
                    mma_f16(acc[mt][nt], af[mt], &bf[nt >> 1][(nt & 1) * 2]);
        }
        __syncthreads();

        int kn = kt + STAGES;
        if (kn < KTILES)
            load_stage(Ag, Bg, sb + (uint32_t)(kn % STAGES) * STG_BYTES, tid, kn * BKH);
        cp_commit();
    }

    // epilogue: fp16 stores (bias folded into scans)
    const int g = lane >> 2, t = lane & 3;
#pragma unroll
    for (int mt = 0; mt < 4; mt++) {
        int r = bm * 128 + wm * 64 + mt * 16 + g;
#pragma unroll
        for (int nt = 0; nt < 8; nt++) {
            int c = bn * 256 + wn * 64 + nt * 8 + 2 * t;
            __half2* p0 = reinterpret_cast<__half2*>(g_Yh + (size_t)r * NTOT + c);
            __half2* p1 = reinterpret_cast<__half2*>(g_Yh + (size_t)(r + 8) * NTOT + c);
            *p0 = __floats2half2_rn(acc[mt][nt][0], acc[mt][nt][1]);
            *p1 = __floats2half2_rn(acc[mt][nt][2], acc[mt][nt][3]);
        }
    }
}

// ---------------------------------------------------------------------------
// Scan phase 1: per-(channel, chunk) affine summary.
__global__ void scan_p1(const float* __restrict__ bias) {
    int idx   = blockIdx.x * blockDim.x + threadIdx.x;
    int ch    = idx & (NCH - 1);
    int chunk = idx >> 14;
    int h = ch & (HID - 1);
    int b = ch >> 10;

    const float bz = bias[h];
    const float bfv = bias[HID + h];

    const __half* __restrict__ Y = g_Yh;
    size_t base = ((size_t)(chunk * CS) * BATCH + b) * NTOT + h;

    float A = 1.f, B = 0.f;
#pragma unroll
    for (int i = 0; i < CS; ++i) {
        float zv = __half2float(Y[base])       + bz;
        float fv = __half2float(Y[base + HID]) + bfv;
        float f = sigmoidf_(fv);
        float z = tanhf_(zv);
        float a = 1.f - f;
        A *= a;
        B = fmaf(a, B, f * z);
        base += (size_t)BATCH * NTOT;
    }
    g_AB[(size_t)idx * 2]     = A;
    g_AB[(size_t)idx * 2 + 1] = B;
}

// Scan phase 2: serial scan over chunk summaries; emit entry carries.
__global__ void scan_p2() {
    int ch = blockIdx.x * blockDim.x + threadIdx.x;
    float c = 0.f;
#pragma unroll 8
    for (int k = 0; k < NC; ++k) {
        size_t idx = (size_t)k * NCH + ch;
        float2 ab = reinterpret_cast<const float2*>(g_AB)[idx];
        g_carry[idx] = c;
        c = fmaf(ab.x, c, ab.y);
    }
}

// Scan phase 3: replay chunk from carry, output gate, write result.
__global__ void scan_p3(const float* __restrict__ bias, float* __restrict__ outp, int slimit) {
    int idx   = blockIdx.x * blockDim.x + threadIdx.x;
    int ch    = idx & (NCH - 1);
    int chunk = idx >> 14;
    int h = ch & (HID - 1);
    int b = ch >> 10;

    const float bz = bias[h];
    const float bfv = bias[HID + h];
    const float bo = bias[2 * HID + h];

    const __half* __restrict__ Y = g_Yh;
    int s0 = chunk * CS;
    size_t base = ((size_t)s0 * BATCH + b) * NTOT + h;
    float c = g_carry[(size_t)chunk * NCH + ch];

#pragma unroll
    for (int i = 0; i < CS; ++i) {
        float zv = __half2float(Y[base])           + bz;
        float fv = __half2float(Y[base + HID])     + bfv;
        float ov = __half2float(Y[base + 2 * HID]) + bo;
        float f = sigmoidf_(fv);
        float z = tanhf_(zv);
        float o = sigmoidf_(ov);
        c = fmaf(f, z - c, c);
        int s = s0 + i;
        if (outp) {
            if (s < slimit)
                outp[(size_t)s * NCH + ch] = o * c;
        } else {
            g_Xh[(size_t)s * NCH + ch] = __float2half(o * c);
        }
        base += (size_t)BATCH * NTOT;
    }
}

// ---------------------------------------------------------------------------
extern "C" void kernel_launch(void* const* d_in, const int* in_sizes, int n_in,
                              void* d_out, int out_size) {
    const int*   x   = (const int*)d_in[0];
    const float* emb = (const float*)d_in[1];
    const float* W[3]  = {(const float*)d_in[2], (const float*)d_in[4], (const float*)d_in[6]};
    const float* bs[3] = {(const float*)d_in[3], (const float*)d_in[5], (const float*)d_in[7]};
    float* out = (float*)d_out;

    cudaFuncSetAttribute(qrnn_gemm_h, cudaFuncAttributeMaxDynamicSharedMemorySize, SMEM_BYTES);

    qrnn_embed<<<(MTOT * 128) / 256, 256>>>(x, emb);

    for (int l = 0; l < 3; l++) {
        w_to_half<<<(NTOT * KTOT / 8) / 256, 256>>>(W[l]);
        qrnn_gemm_h<<<(MTOT / BM) * (NTOT / BN), 256, SMEM_BYTES>>>(0);
        scan_p1<<<(NC * NCH) / 256, 256>>>(bs[l]);
        scan_p2<<<NCH / 128, 128>>>();
        if (l < 2)
            scan_p3<<<(NC * NCH) / 256, 256>>>(bs[l], nullptr, S_LEN);
        else
            scan_p3<<<(NC * NCH) / 256, 256>>>(bs[l], out, S_LEN - 1);
    }
}

// round 17
// speedup vs baseline: 1.0802x; 1.0802x over previous
#include <cuda_runtime.h>
#include <cuda_fp16.h>
#include <cstdint>

// Problem constants
#define S_LEN 2048
#define BATCH 16
#define HID   1024
#define NCH   (BATCH*HID)        // 16384 channels
#define MTOT  (S_LEN*BATCH)      // 32768
#define KTOT  HID                // 1024
#define NTOT  (3*HID)            // 3072

// Scan chunking
#define NC 128
#define CS (S_LEN/NC)            // 16

// fp16 mma GEMM tiling (round-13 shape: 128x128, 2 CTAs/SM)
#define BM 128
#define BN 128
#define BKH 64                   // K halves per stage (=128B row)
#define STAGES 3                 // smem slots; prefetch depth 2, wait_group 1
#define A_BYTES (BM*128)         // 16 KB
#define STG_BYTES (2*A_BYTES)    // 32 KB (A+B)
#define SMEM_BYTES (STAGES*STG_BYTES)   // 96 KB
#define KTILES (KTOT/BKH)        // 16

// Scratch (device globals only)
__device__ __half g_Yh[(size_t)MTOT*NTOT];    // 201 MB : pre-activations (fp16)
__device__ __half g_Xh[(size_t)MTOT*HID];     // 67 MB  : layer input (fp16)
__device__ __half g_Wh[(size_t)NTOT*KTOT];    // 6 MB   : current-layer W (fp16)
__device__ float  g_AB[(size_t)NC*NCH*2];     // 16 MB
__device__ float  g_carry[(size_t)NC*NCH];    // 8 MB

// ---------------------------------------------------------------------------
__device__ __forceinline__ void cp16(uint32_t smem, const void* gmem) {
    asm volatile("cp.async.cg.shared.global [%0], [%1], 16;\n" :: "r"(smem), "l"(gmem));
}
__device__ __forceinline__ void cp_commit() {
    asm volatile("cp.async.commit_group;\n" ::: "memory");
}

__device__ __forceinline__ void ldsm4(uint32_t* r, uint32_t addr) {
    asm volatile("ldmatrix.sync.aligned.m8n8.x4.shared.b16 {%0,%1,%2,%3}, [%4];"
                 : "=r"(r[0]), "=r"(r[1]), "=r"(r[2]), "=r"(r[3]) : "r"(addr));
}

__device__ __forceinline__ void mma_f16(float c[4], const uint32_t a[4], const uint32_t b[2]) {
    asm volatile(
        "mma.sync.aligned.m16n8k16.row.col.f32.f16.f16.f32 "
        "{%0,%1,%2,%3}, {%4,%5,%6,%7}, {%8,%9}, {%0,%1,%2,%3};\n"
        : "+f"(c[0]), "+f"(c[1]), "+f"(c[2]), "+f"(c[3])
        : "r"(a[0]), "r"(a[1]), "r"(a[2]), "r"(a[3]), "r"(b[0]), "r"(b[1]));
}

__device__ __forceinline__ float sigmoidf_(float v) { return 1.f / (1.f + __expf(-v)); }
__device__ __forceinline__ float tanhf_(float v)    { return 2.f / (1.f + __expf(-2.f * v)) - 1.f; }

// ---------------------------------------------------------------------------
// Embedding gather -> fp16
__global__ void qrnn_embed(const int* __restrict__ x, const float* __restrict__ emb) {
    int tid = blockIdx.x * blockDim.x + threadIdx.x;
    int m  = tid >> 7;
    int hv = tid & 127;
    int tok = x[m];
    const float4* src = reinterpret_cast<const float4*>(emb) + (size_t)tok * 256 + hv * 2;
    float4 f0 = src[0], f1 = src[1];
    __half2 h[4];
    h[0] = __floats2half2_rn(f0.x, f0.y);
    h[1] = __floats2half2_rn(f0.z, f0.w);
    h[2] = __floats2half2_rn(f1.x, f1.y);
    h[3] = __floats2half2_rn(f1.z, f1.w);
    *reinterpret_cast<uint4*>(g_Xh + (size_t)m * HID + hv * 8) = *reinterpret_cast<uint4*>(h);
}

// W (fp32) -> g_Wh (fp16)
__global__ void w_to_half(const float* __restrict__ W) {
    int tid = blockIdx.x * blockDim.x + threadIdx.x;
    const float4* src = reinterpret_cast<const float4*>(W) + (size_t)tid * 2;
    float4 f0 = src[0], f1 = src[1];
    __half2 h[4];
    h[0] = __floats2half2_rn(f0.x, f0.y);
    h[1] = __floats2half2_rn(f0.z, f0.w);
    h[2] = __floats2half2_rn(f1.x, f1.y);
    h[3] = __floats2half2_rn(f1.z, f1.w);
    *reinterpret_cast<uint4*>(g_Wh + (size_t)tid * 8) = *reinterpret_cast<uint4*>(h);
}

// ---------------------------------------------------------------------------
// Load one 32KB stage: A 128x64h + B 128x64h, SW128-swizzled (16B granules).
__device__ __forceinline__ void load_stage(const __half* __restrict__ Ag,
                                           const __half* __restrict__ Bg,
                                           uint32_t sstage, int tid, int k0h) {
#pragma unroll
    for (int i = 0; i < 4; i++) {           // A: 1024 16B-chunks
        int c = tid + 256 * i;
        int r = c >> 3, c8 = c & 7;
        cp16(sstage + r * 128 + ((c8 * 16) ^ ((r & 7) << 4)),
             Ag + (size_t)r * KTOT + k0h + c8 * 8);
    }
#pragma unroll
    for (int i = 0; i < 4; i++) {           // B: 1024 16B-chunks
        int c = tid + 256 * i;
        int r = c >> 3, c8 = c & 7;
        cp16(sstage + A_BYTES + r * 128 + ((c8 * 16) ^ ((r & 7) << 4)),
             Bg + (size_t)r * KTOT + k0h + c8 * 8);
    }
}

// ---------------------------------------------------------------------------
// fp16 GEMM: g_Yh[m,n] = sum_k g_Xh[m,k] * g_Wh[n,k]   (fp32 accumulate)
// 8 warps: wm in {0,1} (64 rows), wn in {0..3} (32 cols). 2 CTAs/SM.
// Pipeline: 3 slots, prefetch 2, wait_group 1, ONE barrier per k-tile.
// At iter kt the new load targets slot (kt+2)%3 == (kt-1)%3, which every
// thread finished consuming before reaching this iteration's barrier.
__global__ void __launch_bounds__(256, 2) qrnn_gemm_h(int dummy) {
    extern __shared__ float sm[];
    uint32_t sb = (uint32_t)__cvta_generic_to_shared(sm);
    const int tid = threadIdx.x;
    const int lane = tid & 31;
    const int warp = tid >> 5;
    const int wm = warp & 1;
    const int wn = warp >> 1;

    const int bid = blockIdx.x;
    const int grp = bid / 384;                 // 16 supertiles of 16bm x 24bn
    const int w_  = bid % 384;
    const int bm  = grp * 16 + (w_ & 15);
    const int bn  = w_ >> 4;

    const __half* Ag = g_Xh + (size_t)bm * BM * KTOT;
    const __half* Bg = g_Wh + (size_t)bn * BN * KTOT;

    const uint32_t xorp = (uint32_t)((lane & 7) << 4);
    const uint32_t aRowOff = (uint32_t)((wm * 64 + (lane & 7) + ((lane >> 3) & 1) * 8) * 128);
    const uint32_t bRowOff = (uint32_t)((wn * 32 + (lane & 7) + ((lane >> 4) & 1) * 8) * 128);
    const uint32_t akb = (uint32_t)((lane >> 4) * 16);
    const uint32_t bkb = (uint32_t)(((lane >> 3) & 1) * 16);

    float acc[4][4][4];
#pragma unroll
    for (int i = 0; i < 4; i++)
#pragma unroll
        for (int j = 0; j < 4; j++)
#pragma unroll
            for (int r = 0; r < 4; r++) acc[i][j][r] = 0.f;

    // prefetch 2 stages
    load_stage(Ag, Bg, sb + 0 * STG_BYTES, tid, 0 * BKH);
    cp_commit();
    load_stage(Ag, Bg, sb + 1 * STG_BYTES, tid, 1 * BKH);
    cp_commit();

    for (int kt = 0; kt < KTILES; kt++) {
        asm volatile("cp.async.wait_group 1;\n" ::: "memory");
        __syncthreads();                       // stage kt resident; slot (kt-1)%3 free

        int kn = kt + 2;
        if (kn < KTILES)
            load_stage(Ag, Bg, sb + (uint32_t)(kn % STAGES) * STG_BYTES, tid, kn * BKH);
        cp_commit();

        const uint32_t sA = sb + (uint32_t)(kt % STAGES) * STG_BYTES;
        const uint32_t sB = sA + A_BYTES;

#pragma unroll
        for (int ks = 0; ks < 4; ks++) {
            const uint32_t aK = (uint32_t)(ks * 32 + akb) ^ xorp;
            const uint32_t bK = (uint32_t)(ks * 32 + bkb) ^ xorp;
            uint32_t af[4][4], bf[2][4];
#pragma unroll
            for (int mt = 0; mt < 4; mt++)
                ldsm4(af[mt], sA + aRowOff + mt * 2048 + aK);
#pragma unroll
            for (int np = 0; np < 2; np++)
                ldsm4(bf[np], sB + bRowOff + np * 2048 + bK);
#pragma unroll
            for (int mt = 0; mt < 4; mt++)
#pragma unroll
                for (int nt = 0; nt < 4; nt++)
                    mma_f16(acc[mt][nt], af[mt], &bf[nt >> 1][(nt & 1) * 2]);
        }
    }

    // epilogue: fp16 stores (bias folded into scans)
    const int g = lane >> 2, t = lane & 3;
#pragma unroll
    for (int mt = 0; mt < 4; mt++) {
        int r = bm * 128 + wm * 64 + mt * 16 + g;
#pragma unroll
        for (int nt = 0; nt < 4; nt++) {
            int c = bn * 128 + wn * 32 + nt * 8 + 2 * t;
            __half2* p0 = reinterpret_cast<__half2*>(g_Yh + (size_t)r * NTOT + c);
            __half2* p1 = reinterpret_cast<__half2*>(g_Yh + (size_t)(r + 8) * NTOT + c);
            *p0 = __floats2half2_rn(acc[mt][nt][0], acc[mt][nt][1]);
            *p1 = __floats2half2_rn(acc[mt][nt][2], acc[mt][nt][3]);
        }
    }
}

// ---------------------------------------------------------------------------
// Scan phase 1: per-(channel, chunk) affine summary.
__global__ void scan_p1(const float* __restrict__ bias) {
    int idx   = blockIdx.x * blockDim.x + threadIdx.x;
    int ch    = idx & (NCH - 1);
    int chunk = idx >> 14;
    int h = ch & (HID - 1);
    int b = ch >> 10;

    const float bz = bias[h];
    const float bfv = bias[HID + h];

    const __half* __restrict__ Y = g_Yh;
    size_t base = ((size_t)(chunk * CS) * BATCH + b) * NTOT + h;

    float A = 1.f, B = 0.f;
#pragma unroll
    for (int i = 0; i < CS; ++i) {
        float zv = __half2float(Y[base])       + bz;
        float fv = __half2float(Y[base + HID]) + bfv;
        float f = sigmoidf_(fv);
        float z = tanhf_(zv);
        float a = 1.f - f;
        A *= a;
        B = fmaf(a, B, f * z);
        base += (size_t)BATCH * NTOT;
    }
    g_AB[(size_t)idx * 2]     = A;
    g_AB[(size_t)idx * 2 + 1] = B;
}

// Scan phase 2: serial scan over chunk summaries; emit entry carries.
__global__ void scan_p2() {
    int ch = blockIdx.x * blockDim.x + threadIdx.x;
    float c = 0.f;
#pragma unroll 8
    for (int k = 0; k < NC; ++k) {
        size_t idx = (size_t)k * NCH + ch;
        float2 ab = reinterpret_cast<const float2*>(g_AB)[idx];
        g_carry[idx] = c;
        c = fmaf(ab.x, c, ab.y);
    }
}

// Scan phase 3: replay chunk from carry, output gate, write result.
__global__ void scan_p3(const float* __restrict__ bias, float* __restrict__ outp, int slimit) {
    int idx   = blockIdx.x * blockDim.x + threadIdx.x;
    int ch    = idx & (NCH - 1);
    int chunk = idx >> 14;
    int h = ch & (HID - 1);
    int b = ch >> 10;

    const float bz = bias[h];
    const float bfv = bias[HID + h];
    const float bo = bias[2 * HID + h];

    const __half* __restrict__ Y = g_Yh;
    int s0 = chunk * CS;
    size_t base = ((size_t)s0 * BATCH + b) * NTOT + h;
    float c = g_carry[(size_t)chunk * NCH + ch];

#pragma unroll
    for (int i = 0; i < CS; ++i) {
        float zv = __half2float(Y[base])           + bz;
        float fv = __half2float(Y[base + HID])     + bfv;
        float ov = __half2float(Y[base + 2 * HID]) + bo;
        float f = sigmoidf_(fv);
        float z = tanhf_(zv);
        float o = sigmoidf_(ov);
        c = fmaf(f, z - c, c);
        int s = s0 + i;
        if (outp) {
            if (s < slimit)
                outp[(size_t)s * NCH + ch] = o * c;
        } else {
            g_Xh[(size_t)s * NCH + ch] = __float2half(o * c);
        }
        base += (size_t)BATCH * NTOT;
    }
}

// ---------------------------------------------------------------------------
extern "C" void kernel_launch(void* const* d_in, const int* in_sizes, int n_in,
                              void* d_out, int out_size) {
    const int*   x   = (const int*)d_in[0];
    const float* emb = (const float*)d_in[1];
    const float* W[3]  = {(const float*)d_in[2], (const float*)d_in[4], (const float*)d_in[6]};
    const float* bs[3] = {(const float*)d_in[3], (const float*)d_in[5], (const float*)d_in[7]};
    float* out = (float*)d_out;

    cudaFuncSetAttribute(qrnn_gemm_h, cudaFuncAttributeMaxDynamicSharedMemorySize, SMEM_BYTES);

    qrnn_embed<<<(MTOT * 128) / 256, 256>>>(x, emb);

    for (int l = 0; l < 3; l++) {
        w_to_half<<<(NTOT * KTOT / 8) / 256, 256>>>(W[l]);
        qrnn_gemm_h<<<(MTOT / BM) * (NTOT / BN), 256, SMEM_BYTES>>>(0);
        scan_p1<<<(NC * NCH) / 256, 256>>>(bs[l]);
        scan_p2<<<NCH / 128, 128>>>();
        if (l < 2)
            scan_p3<<<(NC * NCH) / 256, 256>>>(bs[l], nullptr, S_LEN);
        else
            scan_p3<<<(NC * NCH) / 256, 256>>>(bs[l], out, S_LEN - 1);
    }
}